// round 17
// baseline (speedup 1.0000x reference)
#include <cuda_runtime.h>
#include <cuda_bf16.h>
#include <cuda_fp16.h>
#include <cstdint>

// ---------------------------------------------------------------------------
// RelationLayer: L=128, B=16, E=512, C=64, KERNELS={1,3,5,7}, M=256, OUT=256
//  1) prep: conv weights -> fp16, Wuv -> fp16, pair W4 fragments (80B stride)
//  2) G = x(2048x512) @ Wr    (fp16 GEMM, x converted inline, G stored fp16)
//  3) f = lrelu(gather taps + bias) -> fp16
//  4) uv = f(2048x256) @ Wuv  (full-K single-phase)
//  5) pair kernel: pure fp16 MMA, LDS.128 W fragments, half2 epilogues.
// ---------------------------------------------------------------------------

#define LL 128
#define BB 16
#define EE 512
#define MM 256
#define ROWS 2048
#define GCOLS 1024

#define NW (EE * GCOLS)
#define NU (128 * MM)
#define NF (ROWS * MM)

__device__ __half g_Gh[ROWS * GCOLS];
__device__ float g_uv[ROWS * 128];
__device__ __half g_ff[NF];
__device__ __half g_Wrh[NW];
__device__ __half g_Wuvh[NU];
__device__ uint2 g_W4[3840];          // 384 entries x 80B (64B data + 16B pad)

// ===================== helpers ==============================================
__device__ __forceinline__ float lrelu(float x) { return fmaxf(x, 0.1f * x); }

__device__ __forceinline__ uint32_t packh2(float a, float b) {
    __half2 h = __floats2half2_rn(a, b);
    return *(uint32_t*)&h;
}
__device__ __forceinline__ uint32_t hadd2b(uint32_t a, uint32_t b) {
    __half2 r = __hadd2(*(__half2*)&a, *(__half2*)&b);
    return *(uint32_t*)&r;
}
__device__ __forceinline__ uint32_t hlrelu2(uint32_t x, __half2 c01) {
    __half2 xv = *(__half2*)&x;
    __half2 r = __hmax2(xv, __hmul2(xv, c01));
    return *(uint32_t*)&r;
}

// mma.sync m16n8k16 fp16 -> f32 accumulate (baseline PTX)
__device__ __forceinline__ void mmah(float c[4], const uint32_t a[4],
                                     uint32_t b0, uint32_t b1) {
    asm volatile(
        "mma.sync.aligned.m16n8k16.row.col.f32.f16.f16.f32 "
        "{%0,%1,%2,%3}, {%4,%5,%6,%7}, {%8,%9}, {%0,%1,%2,%3};"
        : "+f"(c[0]), "+f"(c[1]), "+f"(c[2]), "+f"(c[3])
        : "r"(a[0]), "r"(a[1]), "r"(a[2]), "r"(a[3]), "r"(b0), "r"(b1));
}

// ===================== prep: Wr/Wuv fp16 + pair W4 fragments ================
__global__ void prep_kernel(const float* __restrict__ cw0,
                            const float* __restrict__ cw1,
                            const float* __restrict__ cw2,
                            const float* __restrict__ cw3,
                            const float* __restrict__ mw0,
                            const float* __restrict__ mw1,
                            const float* __restrict__ mw2,
                            const float* __restrict__ mw3) {
    int idx = blockIdx.x * 256 + threadIdx.x;
    if (idx < NW) {
        int col = idx >> 9;          // n: 0..1023
        int e = idx & 511;           // k
        int p = col >> 6;
        int c = col & 63;
        const float* w; int k, t;
        if (p < 1)      { w = cw0; k = 1; t = p; }
        else if (p < 4) { w = cw1; k = 3; t = p - 1; }
        else if (p < 9) { w = cw2; k = 5; t = p - 4; }
        else            { w = cw3; k = 7; t = p - 9; }
        g_Wrh[idx] = __float2half_rn(w[(c * k + t) * EE + e]);
    } else if (idx < NW + NU) {
        int j = idx - NW;
        int n = j >> 8;              // 0..127
        int k = j & 255;
        float v;
        if (n < 64) v = mw0[n * 512 + k];
        else        v = mw0[(n - 64) * 512 + 256 + k];
        g_Wuvh[j] = __float2half_rn(v);
    } else if (idx < NW + NU + 3072) {
        int e = idx - NW - NU;
        int t4i = e & 3;
        int n = (e >> 2) & 63;       // n = nt*8 + g
        int kc = (e >> 8) & 3;
        int l = e >> 10;
        int nt = n >> 3, g = n & 7;
        const float* wsrc = (l == 0) ? mw1 : (l == 1) ? mw2 : mw3;
        int k0 = kc * 16 + 2 * t4i;
        float2 v01 = *(const float2*)(wsrc + n * 64 + k0);
        float2 v89 = *(const float2*)(wsrc + n * 64 + k0 + 8);
        uint2 pk;
        pk.x = packh2(v01.x, v01.y);
        pk.y = packh2(v89.x, v89.y);
        int e2 = (l * 4 + kc) * 32 + g * 4 + t4i;
        g_W4[e2 * 10 + nt] = pk;
    }
}

// ===================== conv GEMM: x(f32, inline cvt) @ Wr -> G(fp16) ========
#define TSG 72            // padded k-stride in fp16 units

__global__ void __launch_bounds__(256, 1)
gemm_conv_kernel(const float* __restrict__ X,
                 const __half* __restrict__ Bg,
                 __half* __restrict__ Gh) {
    const int N = GCOLS, K = EE;
    constexpr int SA = 0;
    constexpr int SB = 128 * TSG;

    extern __shared__ __half sm[];
    int tid = threadIdx.x, w = tid >> 5, lane = tid & 31;
    int g = lane >> 2, t4 = lane & 3;
    int m0 = blockIdx.y * 128, n0 = blockIdx.x * 128;
    int mw = (w & 3) * 32;
    int nw = (w >> 2) * 64;

    float Cc[2][8][4];
#pragma unroll
    for (int mt = 0; mt < 2; mt++)
#pragma unroll
        for (int nt = 0; nt < 8; nt++)
#pragma unroll
            for (int q = 0; q < 4; q++) Cc[mt][nt][q] = 0.f;

    for (int k0 = 0; k0 < K; k0 += 64) {
        float4 af[8];
        uint4 bv[4];
#pragma unroll
        for (int it = 0; it < 8; it++) {
            int u = tid + it * 256;
            int row = u >> 4;
            int kq = (u & 15) * 4;
            af[it] = *(const float4*)(X + (m0 + row) * K + k0 + kq);
        }
#pragma unroll
        for (int it = 0; it < 4; it++) {
            int u = tid + it * 256;
            int row = u >> 3;
            int kq = (u & 7) * 8;
            bv[it] = *(const uint4*)(Bg + (n0 + row) * K + k0 + kq);
        }
        __syncthreads();
#pragma unroll
        for (int it = 0; it < 8; it++) {
            int u = tid + it * 256;
            int row = u >> 4;
            int kq = (u & 15) * 4;
            uint2 hw;
            hw.x = packh2(af[it].x, af[it].y);
            hw.y = packh2(af[it].z, af[it].w);
            *(uint2*)&sm[SA + row * TSG + kq] = hw;
        }
#pragma unroll
        for (int it = 0; it < 4; it++) {
            int u = tid + it * 256;
            int row = u >> 3;
            int kq = (u & 7) * 8;
            *(uint4*)&sm[SB + row * TSG + kq] = bv[it];
        }
        __syncthreads();

#pragma unroll
        for (int kc = 0; kc < 4; kc++) {
            int kk = kc * 16 + 2 * t4;
            uint32_t A[2][4];
#pragma unroll
            for (int mt = 0; mt < 2; mt++) {
                int r0 = mw + mt * 16 + g;
                int r1 = r0 + 8;
                A[mt][0] = *(const uint32_t*)&sm[SA + r0 * TSG + kk];
                A[mt][1] = *(const uint32_t*)&sm[SA + r1 * TSG + kk];
                A[mt][2] = *(const uint32_t*)&sm[SA + r0 * TSG + kk + 8];
                A[mt][3] = *(const uint32_t*)&sm[SA + r1 * TSG + kk + 8];
            }
#pragma unroll
            for (int nt = 0; nt < 8; nt++) {
                int nrow = nw + nt * 8 + g;
                uint32_t b0 = *(const uint32_t*)&sm[SB + nrow * TSG + kk];
                uint32_t b1 = *(const uint32_t*)&sm[SB + nrow * TSG + kk + 8];
                mmah(Cc[0][nt], A[0], b0, b1);
                mmah(Cc[1][nt], A[1], b0, b1);
            }
        }
    }

#pragma unroll
    for (int mt = 0; mt < 2; mt++) {
        int r0 = m0 + mw + mt * 16 + g;
        int r1 = r0 + 8;
#pragma unroll
        for (int nt = 0; nt < 8; nt++) {
            int col = n0 + nw + nt * 8 + 2 * t4;
            *(uint32_t*)(Gh + r0 * N + col) = packh2(Cc[mt][nt][0], Cc[mt][nt][1]);
            *(uint32_t*)(Gh + r1 * N + col) = packh2(Cc[mt][nt][2], Cc[mt][nt][3]);
        }
    }
}
#define CONV_SMEM_BYTES (2 * 128 * TSG * 2)

// ===================== gather taps -> f (fp16 in/out, ILP 8) ================
__global__ void gather_f_kernel(const float* __restrict__ cb0,
                                const float* __restrict__ cb1,
                                const float* __restrict__ cb2,
                                const float* __restrict__ cb3) {
    int t0 = blockIdx.x * 256 + threadIdx.x;   // 0..65535
#pragma unroll
    for (int q = 0; q < 8; q++) {
        int idx = t0 + q * 65536;
        int row = idx >> 8;        // (l,b): 0..2047
        int m = idx & 255;
        int l = row >> 4, b = row & 15;
        int br = m >> 6, c = m & 63;
        int k, pad, base;
        const float* cb;
        if (br == 0)      { k = 1; base = 0; cb = cb0; }
        else if (br == 1) { k = 3; base = 1; cb = cb1; }
        else if (br == 2) { k = 5; base = 4; cb = cb2; }
        else              { k = 7; base = 9; cb = cb3; }
        pad = (k - 1) >> 1;
        float sum = cb[c];
        for (int tt = 0; tt < k; tt++) {
            int l2 = l - pad + tt;
            if ((unsigned)l2 < (unsigned)LL)
                sum += __half2float(g_Gh[(l2 * BB + b) * GCOLS + (base + tt) * 64 + c]);
        }
        g_ff[idx] = __float2half_rn(lrelu(sum));
    }
}

// ===================== uv GEMM: full-K single-phase fp16 ====================
#define TS2 264           // padded k-stride for K=256

__global__ void __launch_bounds__(256, 1)
gemm_uv_kernel(const __half* __restrict__ Ag,
               const __half* __restrict__ Bg,
               float* __restrict__ C) {
    const int N = 128, K = 256;
    constexpr int SA = 0;
    constexpr int SB = 64 * TS2;

    extern __shared__ __half sm[];
    int tid = threadIdx.x, w = tid >> 5, lane = tid & 31;
    int g = lane >> 2, t4 = lane & 3;
    int m0 = blockIdx.y * 64, n0 = blockIdx.x * 64;
    int mw = (w & 3) * 16;
    int nw = (w >> 2) * 32;

    uint4 av[8], bv[8];
#pragma unroll
    for (int it = 0; it < 8; it++) {
        int u = tid + it * 256;
        int row = u >> 5;
        int kq = (u & 31) * 8;
        av[it] = *(const uint4*)(Ag + (m0 + row) * K + kq);
        bv[it] = *(const uint4*)(Bg + (n0 + row) * K + kq);
    }
#pragma unroll
    for (int it = 0; it < 8; it++) {
        int u = tid + it * 256;
        int row = u >> 5;
        int kq = (u & 31) * 8;
        *(uint4*)&sm[SA + row * TS2 + kq] = av[it];
        *(uint4*)&sm[SB + row * TS2 + kq] = bv[it];
    }
    __syncthreads();

    float Cc[4][4];
#pragma unroll
    for (int nt = 0; nt < 4; nt++)
#pragma unroll
        for (int q = 0; q < 4; q++) Cc[nt][q] = 0.f;

#pragma unroll
    for (int kc = 0; kc < 16; kc++) {
        int kk = kc * 16 + 2 * t4;
        uint32_t A[4];
        int r0 = mw + g, r1 = r0 + 8;
        A[0] = *(const uint32_t*)&sm[SA + r0 * TS2 + kk];
        A[1] = *(const uint32_t*)&sm[SA + r1 * TS2 + kk];
        A[2] = *(const uint32_t*)&sm[SA + r0 * TS2 + kk + 8];
        A[3] = *(const uint32_t*)&sm[SA + r1 * TS2 + kk + 8];
#pragma unroll
        for (int nt = 0; nt < 4; nt++) {
            int nrow = nw + nt * 8 + g;
            uint32_t b0 = *(const uint32_t*)&sm[SB + nrow * TS2 + kk];
            uint32_t b1 = *(const uint32_t*)&sm[SB + nrow * TS2 + kk + 8];
            mmah(Cc[nt], A, b0, b1);
        }
    }

    int r0 = m0 + mw + g, r1 = r0 + 8;
#pragma unroll
    for (int nt = 0; nt < 4; nt++) {
        int col = n0 + nw + nt * 8 + 2 * t4;
        *(float2*)(C + r0 * N + col) = make_float2(Cc[nt][0], Cc[nt][1]);
        *(float2*)(C + r1 * N + col) = make_float2(Cc[nt][2], Cc[nt][3]);
    }
}
#define UV_SMEM_BYTES (2 * 64 * TS2 * 2)

// ===================== pair kernel (half2 epilogues) ========================
// grid (16,16), 128 threads. V fp16 [i][72]; W4 80B-stride packed fragments.
// BH: half2-packed biases for layers 2 and 3 (epilogue path).
#define PVH 72
#define P_W4   0
#define P_V    30720
#define P_U    49152
#define P_B    51200
#define P_BH   52224
#define P_RED  52480
#define P_SR   53504
#define P_TR   55552
#define PAIR_SMEM_BYTES 57600

__global__ void __launch_bounds__(128, 2)
pair_mma_kernel(const float* __restrict__ uv,
                const float* __restrict__ mb0, const float* __restrict__ mb1,
                const float* __restrict__ mb2, const float* __restrict__ mb3,
                const float* __restrict__ lw0, const float* __restrict__ lb0,
                const float* __restrict__ lw1, const float* __restrict__ lb1,
                float* __restrict__ out) {
    extern __shared__ char smp[];
    int tid = threadIdx.x, w = tid >> 5, lane = tid & 31;
    int g = lane >> 2, t4 = lane & 3;
    int b = blockIdx.y, j0 = blockIdx.x * 8;
    const __half2 c01 = __float2half2_rn(0.1f);

    // ---- stage prepacked W4 fragments (flat uint4 copy: 1920 uint4) ----
    {
        uint4* dst = (uint4*)(smp + P_W4);
        const uint4* src = (const uint4*)g_W4;
#pragma unroll
        for (int q = 0; q < 15; q++)
            dst[tid + 128 * q] = src[tid + 128 * q];
    }
    // ---- stage V as fp16 [i][PVH]: thread = row i ----
    {
        __half* Vh = (__half*)(smp + P_V);
        const float* vp = uv + (tid * BB + b) * 128 + 64;
#pragma unroll
        for (int q = 0; q < 16; q++) {
            float4 v4 = *(const float4*)(vp + q * 4);
            uint2 hw;
            hw.x = packh2(v4.x, v4.y);
            hw.y = packh2(v4.z, v4.w);
            *(uint2*)&Vh[tid * PVH + q * 4] = hw;
        }
    }
    if (tid < 64) {
        float* U = (float*)(smp + P_U);
#pragma unroll
        for (int jt = 0; jt < 8; jt++)
            U[jt * 64 + tid] = uv[((j0 + jt) * BB + b) * 128 + tid];
        float* Bs = (float*)(smp + P_B);
        Bs[tid] = mb0[tid];
        Bs[64 + tid] = mb1[tid];
        Bs[128 + tid] = mb2[tid];
        Bs[192 + tid] = mb3[tid];
    }
    if (tid < 32) {
        uint32_t* BH = (uint32_t*)(smp + P_BH);
        BH[tid]      = packh2(mb1[2 * tid], mb1[2 * tid + 1]);
        BH[32 + tid] = packh2(mb2[2 * tid], mb2[2 * tid + 1]);
    }
    __syncthreads();

    const __half* Vh = (const __half*)(smp + P_V);
    const float* U = (const float*)(smp + P_U);
    const float* BIAS = (const float*)(smp + P_B);
    const uint32_t* BH = (const uint32_t*)(smp + P_BH);
    const char* W4p = smp + P_W4;
    float* RED = (float*)(smp + P_RED);
    float* SR = (float*)(smp + P_SR);
    int g4t80 = (g * 4 + t4) * 80;

    for (int jt = 0; jt < 8; jt++) {
        uint32_t A[2][4][4];

        // ---- layer-1 A fragments: x = lrelu(fp16(u+b0) + v), half2 path ----
#pragma unroll
        for (int kc = 0; kc < 4; kc++) {
            int k0 = kc * 16 + 2 * t4;
            float2 u01 = *(const float2*)&U[jt * 64 + k0];
            float2 u89 = *(const float2*)&U[jt * 64 + k0 + 8];
            float2 b01 = *(const float2*)&BIAS[k0];
            float2 b89 = *(const float2*)&BIAS[k0 + 8];
            uint32_t uh01 = packh2(u01.x + b01.x, u01.y + b01.y);
            uint32_t uh89 = packh2(u89.x + b89.x, u89.y + b89.y);
#pragma unroll
            for (int mt = 0; mt < 2; mt++) {
                int r0 = w * 32 + mt * 16 + g;
                int r1 = r0 + 8;
                uint32_t va0 = *(const uint32_t*)&Vh[r0 * PVH + k0];
                uint32_t va8 = *(const uint32_t*)&Vh[r0 * PVH + k0 + 8];
                uint32_t vb0 = *(const uint32_t*)&Vh[r1 * PVH + k0];
                uint32_t vb8 = *(const uint32_t*)&Vh[r1 * PVH + k0 + 8];
                A[mt][kc][0] = hlrelu2(hadd2b(uh01, va0), c01);
                A[mt][kc][1] = hlrelu2(hadd2b(uh01, vb0), c01);
                A[mt][kc][2] = hlrelu2(hadd2b(uh89, va8), c01);
                A[mt][kc][3] = hlrelu2(hadd2b(uh89, vb8), c01);
            }
        }

        // ---- 3 chained MMA layers (single-term: A*W, LDS.128 frags) ----
        float Cc[2][8][4];
#pragma unroll
        for (int l = 0; l < 3; l++) {
#pragma unroll
            for (int mt = 0; mt < 2; mt++)
#pragma unroll
                for (int nt = 0; nt < 8; nt++)
#pragma unroll
                    for (int q = 0; q < 4; q++) Cc[mt][nt][q] = 0.f;

#pragma unroll
            for (int kc = 0; kc < 4; kc++) {
                const char* wb = W4p + (l * 4 + kc) * 32 * 80 + g4t80;
#pragma unroll
                for (int ntp = 0; ntp < 4; ntp++) {
                    uint4 wq = *(const uint4*)(wb + ntp * 16);
                    mmah(Cc[0][2 * ntp],     A[0][kc], wq.x, wq.y);
                    mmah(Cc[1][2 * ntp],     A[1][kc], wq.x, wq.y);
                    mmah(Cc[0][2 * ntp + 1], A[0][kc], wq.z, wq.w);
                    mmah(Cc[1][2 * ntp + 1], A[1][kc], wq.z, wq.w);
                }
            }

            if (l < 2) {
                const uint32_t* bh = BH + 32 * l;
#pragma unroll
                for (int nt = 0; nt < 8; nt++) {
                    uint32_t bp = bh[nt * 4 + t4];
                    int kc2 = nt >> 1, ri = (nt & 1) * 2;
#pragma unroll
                    for (int mt = 0; mt < 2; mt++) {
                        A[mt][kc2][ri] = hlrelu2(
                            hadd2b(packh2(Cc[mt][nt][0], Cc[mt][nt][1]), bp), c01);
                        A[mt][kc2][ri + 1] = hlrelu2(
                            hadd2b(packh2(Cc[mt][nt][2], Cc[mt][nt][3]), bp), c01);
                    }
                }
            }
        }

        // ---- final: bias + lrelu (f32), reduce over i ----
        {
            const float* bl = BIAS + 192;
#pragma unroll
            for (int nt = 0; nt < 8; nt++) {
                int col = nt * 8 + 2 * t4;
                float bx = bl[col], by = bl[col + 1];
                float s0 = lrelu(Cc[0][nt][0] + bx) + lrelu(Cc[0][nt][2] + bx) +
                           lrelu(Cc[1][nt][0] + bx) + lrelu(Cc[1][nt][2] + bx);
                float s1 = lrelu(Cc[0][nt][1] + by) + lrelu(Cc[0][nt][3] + by) +
                           lrelu(Cc[1][nt][1] + by) + lrelu(Cc[1][nt][3] + by);
                s0 += __shfl_xor_sync(0xffffffffu, s0, 4);
                s0 += __shfl_xor_sync(0xffffffffu, s0, 8);
                s0 += __shfl_xor_sync(0xffffffffu, s0, 16);
                s1 += __shfl_xor_sync(0xffffffffu, s1, 4);
                s1 += __shfl_xor_sync(0xffffffffu, s1, 8);
                s1 += __shfl_xor_sync(0xffffffffu, s1, 16);
                if (lane < 4) {
                    RED[w * 64 + col] = s0;
                    RED[w * 64 + col + 1] = s1;
                }
            }
        }
        __syncthreads();
        if (tid < 64) {
            float s = RED[tid] + RED[64 + tid] + RED[128 + tid] + RED[192 + tid];
            SR[jt * 64 + tid] = s;
        }
        __syncthreads();
    }

    // ---- fused head: t = lrelu(s@lw0.T+lb0); out = lrelu(t@lw1.T+lb1) ----
    float* TR = (float*)(smp + P_TR);
#pragma unroll
    for (int q = 0; q < 4; q++) {
        int idx = tid + 128 * q;
        int jt = idx >> 6, o = idx & 63;
        const float* wr = lw0 + o * 64;
        float acc = lb0[o];
#pragma unroll
        for (int c = 0; c < 64; c += 4) {
            float4 w4 = *(const float4*)(wr + c);
            acc += SR[jt * 64 + c] * w4.x + SR[jt * 64 + c + 1] * w4.y +
                   SR[jt * 64 + c + 2] * w4.z + SR[jt * 64 + c + 3] * w4.w;
        }
        TR[idx] = lrelu(acc);
    }
    __syncthreads();
#pragma unroll
    for (int q = 0; q < 16; q++) {
        int idx = tid + 128 * q;
        int jt = idx >> 8, o = idx & 255;
        const float* wr = lw1 + o * 64;
        float acc = lb1[o];
#pragma unroll
        for (int c = 0; c < 64; c += 4) {
            float4 w4 = *(const float4*)(wr + c);
            acc += TR[jt * 64 + c] * w4.x + TR[jt * 64 + c + 1] * w4.y +
                   TR[jt * 64 + c + 2] * w4.z + TR[jt * 64 + c + 3] * w4.w;
        }
        out[((j0 + jt) * BB + b) * 256 + o] = lrelu(acc);
    }
}

// ===================== host launch ==========================================
extern "C" void kernel_launch(void* const* d_in, const int* in_sizes, int n_in,
                              void* d_out, int out_size) {
    const float* x   = (const float*)d_in[0];
    const float* cw0 = (const float*)d_in[1];
    const float* cb0 = (const float*)d_in[2];
    const float* cw1 = (const float*)d_in[3];
    const float* cb1 = (const float*)d_in[4];
    const float* cw2 = (const float*)d_in[5];
    const float* cb2 = (const float*)d_in[6];
    const float* cw3 = (const float*)d_in[7];
    const float* cb3 = (const float*)d_in[8];
    const float* mw0 = (const float*)d_in[9];
    const float* mb0 = (const float*)d_in[10];
    const float* mw1 = (const float*)d_in[11];
    const float* mb1 = (const float*)d_in[12];
    const float* mw2 = (const float*)d_in[13];
    const float* mb2 = (const float*)d_in[14];
    const float* mw3 = (const float*)d_in[15];
    const float* mb3 = (const float*)d_in[16];
    const float* lw0 = (const float*)d_in[17];
    const float* lb0 = (const float*)d_in[18];
    const float* lw1 = (const float*)d_in[19];
    const float* lb1 = (const float*)d_in[20];
    float* out = (float*)d_out;

    float* uvb;
    __half *Gh, *ff, *Wrh, *Wuvh;
    cudaGetSymbolAddress((void**)&Gh, g_Gh);
    cudaGetSymbolAddress((void**)&uvb, g_uv);
    cudaGetSymbolAddress((void**)&ff, g_ff);
    cudaGetSymbolAddress((void**)&Wrh, g_Wrh);
    cudaGetSymbolAddress((void**)&Wuvh, g_Wuvh);

    // 1) prep (weights + pair W4 fragments)
    prep_kernel<<<(NW + NU + 3072 + 255) / 256, 256>>>(
        cw0, cw1, cw2, cw3, mw0, mw1, mw2, mw3);

    // 2) conv as GEMM: G = x @ Wr (x cvt inline, G fp16)
    cudaFuncSetAttribute(gemm_conv_kernel,
                         cudaFuncAttributeMaxDynamicSharedMemorySize,
                         CONV_SMEM_BYTES);
    gemm_conv_kernel<<<dim3(GCOLS / 128, ROWS / 128), 256, CONV_SMEM_BYTES>>>(
        x, Wrh, Gh);

    // 3) gather taps -> f (fp16)
    gather_f_kernel<<<256, 256>>>(cb0, cb1, cb2, cb3);

    // 4) uv = f @ Wuv (full-K single-phase, 64x64 tiles)
    cudaFuncSetAttribute(gemm_uv_kernel,
                         cudaFuncAttributeMaxDynamicSharedMemorySize,
                         UV_SMEM_BYTES);
    gemm_uv_kernel<<<dim3(2, ROWS / 64), 256, UV_SMEM_BYTES>>>(
        ff, Wuvh, uvb);

    // 5) pair stage + fused head
    cudaFuncSetAttribute(pair_mma_kernel,
                         cudaFuncAttributeMaxDynamicSharedMemorySize,
                         PAIR_SMEM_BYTES);
    pair_mma_kernel<<<dim3(16, 16), 128, PAIR_SMEM_BYTES>>>(
        uvb, mb0, mb1, mb2, mb3, lw0, lb0, lw1, lb1, out);
}